// round 8
// baseline (speedup 1.0000x reference)
#include <cuda_runtime.h>
#include <cstddef>

#define TPB 128              // 4 warps/block, each warp owns 32 elements
#define STRIDE 46            // floats per element row in smem (max chunk 44)

static constexpr int NB = 131072;

// ---------------------------------------------------------------------------
// Compile-time Clebsch-Gordan coefficients (Racah formula), double precision,
// evaluated entirely by the compiler (constexpr Newton sqrt).
// ---------------------------------------------------------------------------
__host__ __device__ constexpr double factd(int n) {
    double r = 1.0;
    for (int i = 2; i <= n; ++i) r *= (double)i;
    return r;
}
__host__ __device__ constexpr double csqrt(double x) {
    if (x <= 0.0) return 0.0;
    double g = x > 1.0 ? x : 1.0;
    for (int i = 0; i < 100; ++i) g = 0.5 * (g + x / g);
    return g;
}
__host__ __device__ constexpr int iabs_c(int x) { return x < 0 ? -x : x; }
__host__ __device__ constexpr int imin6(int a, int b, int c, int d, int e, int f) {
    int m = a;
    if (b < m) m = b; if (c < m) m = c; if (d < m) m = d;
    if (e < m) m = e; if (f < m) m = f;
    return m;
}

__host__ __device__ constexpr double cgco(int j1, int m1, int j2, int m2, int j, int m) {
    if (m1 + m2 != m) return 0.0;
    if (j < iabs_c(j1 - j2) || j > j1 + j2) return 0.0;
    if (iabs_c(m) > j || iabs_c(m1) > j1 || iabs_c(m2) > j2) return 0.0;
    double pre = csqrt((2.0 * j + 1.0) * factd(j1 + j2 - j) * factd(j + j1 - j2) *
                       factd(j + j2 - j1) / factd(j1 + j2 + j + 1));
    pre *= csqrt(factd(j + m) * factd(j - m) * factd(j1 + m1) * factd(j1 - m1) *
                 factd(j2 + m2) * factd(j2 - m2));
    double s = 0.0;
    for (int k = 0; k <= j1 + j2 - j; ++k) {
        const int d1 = k;
        const int d2 = j1 + j2 - j - k;
        const int d3 = j1 - m1 - k;
        const int d4 = j2 + m2 - k;
        const int d5 = j - j2 + m1 + k;
        const int d6 = j - j1 - m2 + k;
        if (imin6(d1, d2, d3, d4, d5, d6) < 0) continue;
        const double denom = factd(d1) * factd(d2) * factd(d3) * factd(d4) * factd(d5) * factd(d6);
        s += ((k & 1) ? -1.0 : 1.0) / denom;
    }
    return pre * s;
}

// Register-array offset for input part l (sizes 1,3,5,7 -> offsets 0,1,4,9)
template <int L>
__host__ __device__ constexpr int xoff() { return L == 0 ? 0 : (L == 1 ? 1 : (L == 2 ? 4 : 9)); }

// ---------------------------------------------------------------------------
// Template-unrolled accumulation: sum over m1 for one (l1,l2,l,m) entry set.
// All CG coefficients become FFMA immediates; zero coefficients pruned.
// ---------------------------------------------------------------------------
template <int L1, int L2, int L, int M, int M1>
__device__ __forceinline__ void acc_m1(float& fr, float& fi, const float* xr, const float* xi) {
    constexpr int M2 = M - M1;
    if constexpr (M2 >= -L2 && M2 <= L2) {
        constexpr double Cd = cgco(L1, M1, L2, M2, L, M);
        if constexpr (Cd != 0.0) {
            constexpr float C = (float)Cd;
            const float a = xr[xoff<L1>() + M1 + L1];
            const float b = xi[xoff<L1>() + M1 + L1];
            const float c = xr[xoff<L2>() + M2 + L2];
            const float d = xi[xoff<L2>() + M2 + L2];
            const float pr = fmaf(-b, d, a * c);   // Re(x*y)
            const float pi = fmaf( b, c, a * d);   // Im(x*y)
            fr = fmaf(C, pr, fr);
            fi = fmaf(C, pi, fi);
        }
    }
    if constexpr (M1 < L1) acc_m1<L1, L2, L, M, M1 + 1>(fr, fi, xr, xi);
}

// One fragment (l1,l2) contributing to output l, for m in [MLO, MHI].
// Writes (fr,fi) into the lane's smem row at chunk position ((m-MLO)*TAU+FI)*2.
template <int L, int TAU, int FI, int L1, int L2, int MLO, int MHI, int M>
__device__ __forceinline__ void frag_ms(float* row, const float* xr, const float* xi) {
    float fr = 0.0f, fi2 = 0.0f;
    acc_m1<L1, L2, L, M, (-L1)>(fr, fi2, xr, xi);
    row[((M - MLO) * TAU + FI) * 2 + 0] = fr;
    row[((M - MLO) * TAU + FI) * 2 + 1] = fi2;
    if constexpr (M < MHI) frag_ms<L, TAU, FI, L1, L2, MLO, MHI, M + 1>(row, xr, xi);
}

// Per-WARP cooperative coalesced store of one staged chunk (32 rows).
// CHUNK floats per element (even), OFF = float offset inside the 512-float row.
// Fully unrolled: C2 independent LDS.64 -> STG.64 pairs for max MLP.
template <int CHUNK, int OFF>
__device__ __forceinline__ void store_stage(const float* smw, float* __restrict__ out,
                                            int wbase, int lane) {
    __syncwarp();
    constexpr int C2 = CHUNK / 2;
    #pragma unroll
    for (int it = 0; it < C2; ++it) {
        const int u = it * 32 + lane;
        const int e = u / C2;
        const int j = u - e * C2;
        const float2 v = *reinterpret_cast<const float2*>(smw + e * STRIDE + 2 * j);
        *reinterpret_cast<float2*>(out + (size_t)(wbase + e) * 512 + OFF + 2 * j) = v;
    }
    __syncwarp();
}

// ---------------------------------------------------------------------------
// Main kernel: one thread per batch element; warp-private smem staging.
// Output layout per element (512 floats):
//   l=0: off   0, tau 4  | l=1: off   8, tau 9 | l=2: off  62, tau 11
//   l=3: off 172, tau 10 | l=4: off 312, tau 6 | l=5: off 420, tau 3
//   l=6: off 486, tau 1
// Stages split by m so each smem stage chunk is <= 44 floats/element.
// 5 CTAs/SM => 102-reg cap: no spills (live set ~80), 20 warps/SM.
// ---------------------------------------------------------------------------
__global__ void __launch_bounds__(TPB, 5)
cgprod_kernel(const float* __restrict__ x0, const float* __restrict__ x1,
              const float* __restrict__ x2, const float* __restrict__ x3,
              float* __restrict__ out) {
    __shared__ float sm[TPB * STRIDE];
    const int tid   = threadIdx.x;
    const int lane  = tid & 31;
    const int warp  = tid >> 5;
    const int wbase = blockIdx.x * TPB + warp * 32;   // first element of this warp
    const int b     = wbase + lane;

    float xr[16], xi[16];
    {
        const float2 v = reinterpret_cast<const float2*>(x0)[b];
        xr[0] = v.x; xi[0] = v.y;
    }
    {
        const float2* p = reinterpret_cast<const float2*>(x1) + (size_t)b * 3;
        #pragma unroll
        for (int k = 0; k < 3; ++k) { const float2 v = p[k]; xr[1 + k] = v.x; xi[1 + k] = v.y; }
    }
    {
        const float2* p = reinterpret_cast<const float2*>(x2) + (size_t)b * 5;
        #pragma unroll
        for (int k = 0; k < 5; ++k) { const float2 v = p[k]; xr[4 + k] = v.x; xi[4 + k] = v.y; }
    }
    {
        const float2* p = reinterpret_cast<const float2*>(x3) + (size_t)b * 7;
        #pragma unroll
        for (int k = 0; k < 7; ++k) { const float2 v = p[k]; xr[9 + k] = v.x; xi[9 + k] = v.y; }
    }

    float* smw = sm + warp * 32 * STRIDE;   // this warp's 32-row staging region
    float* row = smw + lane * STRIDE;       // this lane's row

    // ---- l = 0 (tau=4), m = 0: chunk 8 @ off 0 ----
    {
        constexpr int L = 0, TAU = 4, MLO = 0, MHI = 0;
        frag_ms<L, TAU, 0, 0, 0, MLO, MHI, MLO>(row, xr, xi);
        frag_ms<L, TAU, 1, 1, 1, MLO, MHI, MLO>(row, xr, xi);
        frag_ms<L, TAU, 2, 2, 2, MLO, MHI, MLO>(row, xr, xi);
        frag_ms<L, TAU, 3, 3, 3, MLO, MHI, MLO>(row, xr, xi);
    }
    store_stage<8, 0>(smw, out, wbase, lane);

    // ---- l = 1 (tau=9) ----
    #define L1_FRAGS(MLO, MHI)                                   \
        { constexpr int L = 1, TAU = 9;                          \
          frag_ms<L, TAU, 0, 0, 1, MLO, MHI, MLO>(row, xr, xi);  \
          frag_ms<L, TAU, 1, 1, 0, MLO, MHI, MLO>(row, xr, xi);  \
          frag_ms<L, TAU, 2, 1, 1, MLO, MHI, MLO>(row, xr, xi);  \
          frag_ms<L, TAU, 3, 1, 2, MLO, MHI, MLO>(row, xr, xi);  \
          frag_ms<L, TAU, 4, 2, 1, MLO, MHI, MLO>(row, xr, xi);  \
          frag_ms<L, TAU, 5, 2, 2, MLO, MHI, MLO>(row, xr, xi);  \
          frag_ms<L, TAU, 6, 2, 3, MLO, MHI, MLO>(row, xr, xi);  \
          frag_ms<L, TAU, 7, 3, 2, MLO, MHI, MLO>(row, xr, xi);  \
          frag_ms<L, TAU, 8, 3, 3, MLO, MHI, MLO>(row, xr, xi); }
    L1_FRAGS(-1, 0)  store_stage<36, 8>(smw, out, wbase, lane);    // m=-1..0
    L1_FRAGS( 1, 1)  store_stage<18, 44>(smw, out, wbase, lane);   // m=1

    // ---- l = 2 (tau=11) ----
    #define L2_FRAGS(MLO, MHI)                                    \
        { constexpr int L = 2, TAU = 11;                          \
          frag_ms<L, TAU,  0, 0, 2, MLO, MHI, MLO>(row, xr, xi);  \
          frag_ms<L, TAU,  1, 1, 1, MLO, MHI, MLO>(row, xr, xi);  \
          frag_ms<L, TAU,  2, 1, 2, MLO, MHI, MLO>(row, xr, xi);  \
          frag_ms<L, TAU,  3, 1, 3, MLO, MHI, MLO>(row, xr, xi);  \
          frag_ms<L, TAU,  4, 2, 0, MLO, MHI, MLO>(row, xr, xi);  \
          frag_ms<L, TAU,  5, 2, 1, MLO, MHI, MLO>(row, xr, xi);  \
          frag_ms<L, TAU,  6, 2, 2, MLO, MHI, MLO>(row, xr, xi);  \
          frag_ms<L, TAU,  7, 2, 3, MLO, MHI, MLO>(row, xr, xi);  \
          frag_ms<L, TAU,  8, 3, 1, MLO, MHI, MLO>(row, xr, xi);  \
          frag_ms<L, TAU,  9, 3, 2, MLO, MHI, MLO>(row, xr, xi);  \
          frag_ms<L, TAU, 10, 3, 3, MLO, MHI, MLO>(row, xr, xi); }
    L2_FRAGS(-2, -1) store_stage<44, 62>(smw, out, wbase, lane);   // m=-2..-1
    L2_FRAGS( 0,  1) store_stage<44, 106>(smw, out, wbase, lane);  // m=0..1
    L2_FRAGS( 2,  2) store_stage<22, 150>(smw, out, wbase, lane);  // m=2

    // ---- l = 3 (tau=10) ----
    #define L3_FRAGS(MLO, MHI)                                   \
        { constexpr int L = 3, TAU = 10;                         \
          frag_ms<L, TAU, 0, 0, 3, MLO, MHI, MLO>(row, xr, xi);  \
          frag_ms<L, TAU, 1, 1, 2, MLO, MHI, MLO>(row, xr, xi);  \
          frag_ms<L, TAU, 2, 1, 3, MLO, MHI, MLO>(row, xr, xi);  \
          frag_ms<L, TAU, 3, 2, 1, MLO, MHI, MLO>(row, xr, xi);  \
          frag_ms<L, TAU, 4, 2, 2, MLO, MHI, MLO>(row, xr, xi);  \
          frag_ms<L, TAU, 5, 2, 3, MLO, MHI, MLO>(row, xr, xi);  \
          frag_ms<L, TAU, 6, 3, 0, MLO, MHI, MLO>(row, xr, xi);  \
          frag_ms<L, TAU, 7, 3, 1, MLO, MHI, MLO>(row, xr, xi);  \
          frag_ms<L, TAU, 8, 3, 2, MLO, MHI, MLO>(row, xr, xi);  \
          frag_ms<L, TAU, 9, 3, 3, MLO, MHI, MLO>(row, xr, xi); }
    L3_FRAGS(-3, -2) store_stage<40, 172>(smw, out, wbase, lane);  // m=-3..-2
    L3_FRAGS(-1,  0) store_stage<40, 212>(smw, out, wbase, lane);  // m=-1..0
    L3_FRAGS( 1,  2) store_stage<40, 252>(smw, out, wbase, lane);  // m=1..2
    L3_FRAGS( 3,  3) store_stage<20, 292>(smw, out, wbase, lane);  // m=3

    // ---- l = 4 (tau=6) ----
    #define L4_FRAGS(MLO, MHI)                                   \
        { constexpr int L = 4, TAU = 6;                          \
          frag_ms<L, TAU, 0, 1, 3, MLO, MHI, MLO>(row, xr, xi);  \
          frag_ms<L, TAU, 1, 2, 2, MLO, MHI, MLO>(row, xr, xi);  \
          frag_ms<L, TAU, 2, 2, 3, MLO, MHI, MLO>(row, xr, xi);  \
          frag_ms<L, TAU, 3, 3, 1, MLO, MHI, MLO>(row, xr, xi);  \
          frag_ms<L, TAU, 4, 3, 2, MLO, MHI, MLO>(row, xr, xi);  \
          frag_ms<L, TAU, 5, 3, 3, MLO, MHI, MLO>(row, xr, xi); }
    L4_FRAGS(-4, -2) store_stage<36, 312>(smw, out, wbase, lane);  // m=-4..-2
    L4_FRAGS(-1,  1) store_stage<36, 348>(smw, out, wbase, lane);  // m=-1..1
    L4_FRAGS( 2,  4) store_stage<36, 384>(smw, out, wbase, lane);  // m=2..4

    // ---- l = 5 (tau=3) ----
    #define L5_FRAGS(MLO, MHI)                                   \
        { constexpr int L = 5, TAU = 3;                          \
          frag_ms<L, TAU, 0, 2, 3, MLO, MHI, MLO>(row, xr, xi);  \
          frag_ms<L, TAU, 1, 3, 2, MLO, MHI, MLO>(row, xr, xi);  \
          frag_ms<L, TAU, 2, 3, 3, MLO, MHI, MLO>(row, xr, xi); }
    L5_FRAGS(-5, 1)  store_stage<42, 420>(smw, out, wbase, lane);  // m=-5..1
    L5_FRAGS( 2, 5)  store_stage<24, 462>(smw, out, wbase, lane);  // m=2..5

    // ---- l = 6 (tau=1), m = -6..6: chunk 26 @ off 486 ----
    {
        constexpr int L = 6, TAU = 1, MLO = -6, MHI = 6;
        frag_ms<L, TAU, 0, 3, 3, MLO, MHI, MLO>(row, xr, xi);
    }
    store_stage<26, 486>(smw, out, wbase, lane);
}

extern "C" void kernel_launch(void* const* d_in, const int* in_sizes, int n_in,
                              void* d_out, int out_size) {
    // Defensive: map inputs by element count (all four are distinct).
    const float* xp[4] = {nullptr, nullptr, nullptr, nullptr};
    for (int i = 0; i < n_in && i < 8; ++i) {
        const int s = in_sizes[i];
        if      (s == NB * 2)  xp[0] = (const float*)d_in[i];
        else if (s == NB * 6)  xp[1] = (const float*)d_in[i];
        else if (s == NB * 10) xp[2] = (const float*)d_in[i];
        else if (s == NB * 14) xp[3] = (const float*)d_in[i];
    }
    cgprod_kernel<<<NB / TPB, TPB>>>(xp[0], xp[1], xp[2], xp[3], (float*)d_out);
}

// round 9
// speedup vs baseline: 1.9983x; 1.9983x over previous
#include <cuda_runtime.h>
#include <cstddef>

#define TPB 128              // 4 warps/block, each warp owns 32 elements
#define STRIDE 46            // floats per element row in smem (max chunk 44)

static constexpr int NB = 131072;

// ---------------------------------------------------------------------------
// Compile-time Clebsch-Gordan coefficients (Racah formula), double precision,
// evaluated entirely by the compiler (constexpr Newton sqrt).
// ---------------------------------------------------------------------------
__host__ __device__ constexpr double factd(int n) {
    double r = 1.0;
    for (int i = 2; i <= n; ++i) r *= (double)i;
    return r;
}
__host__ __device__ constexpr double csqrt(double x) {
    if (x <= 0.0) return 0.0;
    double g = x > 1.0 ? x : 1.0;
    for (int i = 0; i < 100; ++i) g = 0.5 * (g + x / g);
    return g;
}
__host__ __device__ constexpr int iabs_c(int x) { return x < 0 ? -x : x; }
__host__ __device__ constexpr int imin6(int a, int b, int c, int d, int e, int f) {
    int m = a;
    if (b < m) m = b; if (c < m) m = c; if (d < m) m = d;
    if (e < m) m = e; if (f < m) m = f;
    return m;
}

__host__ __device__ constexpr double cgco(int j1, int m1, int j2, int m2, int j, int m) {
    if (m1 + m2 != m) return 0.0;
    if (j < iabs_c(j1 - j2) || j > j1 + j2) return 0.0;
    if (iabs_c(m) > j || iabs_c(m1) > j1 || iabs_c(m2) > j2) return 0.0;
    double pre = csqrt((2.0 * j + 1.0) * factd(j1 + j2 - j) * factd(j + j1 - j2) *
                       factd(j + j2 - j1) / factd(j1 + j2 + j + 1));
    pre *= csqrt(factd(j + m) * factd(j - m) * factd(j1 + m1) * factd(j1 - m1) *
                 factd(j2 + m2) * factd(j2 - m2));
    double s = 0.0;
    for (int k = 0; k <= j1 + j2 - j; ++k) {
        const int d1 = k;
        const int d2 = j1 + j2 - j - k;
        const int d3 = j1 - m1 - k;
        const int d4 = j2 + m2 - k;
        const int d5 = j - j2 + m1 + k;
        const int d6 = j - j1 - m2 + k;
        if (imin6(d1, d2, d3, d4, d5, d6) < 0) continue;
        const double denom = factd(d1) * factd(d2) * factd(d3) * factd(d4) * factd(d5) * factd(d6);
        s += ((k & 1) ? -1.0 : 1.0) / denom;
    }
    return pre * s;
}

// Register-array offset for input part l (sizes 1,3,5,7 -> offsets 0,1,4,9)
template <int L>
__host__ __device__ constexpr int xoff() { return L == 0 ? 0 : (L == 1 ? 1 : (L == 2 ? 4 : 9)); }

// ---------------------------------------------------------------------------
// Template-unrolled accumulation: sum over m1 for one (l1,l2,l,m) entry set.
// All CG coefficients become FFMA immediates; zero coefficients pruned.
// ---------------------------------------------------------------------------
template <int L1, int L2, int L, int M, int M1>
__device__ __forceinline__ void acc_m1(float& fr, float& fi, const float* xr, const float* xi) {
    constexpr int M2 = M - M1;
    if constexpr (M2 >= -L2 && M2 <= L2) {
        constexpr double Cd = cgco(L1, M1, L2, M2, L, M);
        if constexpr (Cd != 0.0) {
            constexpr float C = (float)Cd;
            const float a = xr[xoff<L1>() + M1 + L1];
            const float b = xi[xoff<L1>() + M1 + L1];
            const float c = xr[xoff<L2>() + M2 + L2];
            const float d = xi[xoff<L2>() + M2 + L2];
            const float pr = fmaf(-b, d, a * c);   // Re(x*y)
            const float pi = fmaf( b, c, a * d);   // Im(x*y)
            fr = fmaf(C, pr, fr);
            fi = fmaf(C, pi, fi);
        }
    }
    if constexpr (M1 < L1) acc_m1<L1, L2, L, M, M1 + 1>(fr, fi, xr, xi);
}

// One fragment (l1,l2) contributing to output l, for m in [MLO, MHI].
// Writes (fr,fi) as ONE float2 (STS.64) into the lane's smem row at
// chunk position ((m-MLO)*TAU+FI)*2 — always 8B-aligned (even float index).
template <int L, int TAU, int FI, int L1, int L2, int MLO, int MHI, int M>
__device__ __forceinline__ void frag_ms(float* row, const float* xr, const float* xi) {
    float fr = 0.0f, fi2 = 0.0f;
    acc_m1<L1, L2, L, M, (-L1)>(fr, fi2, xr, xi);
    *reinterpret_cast<float2*>(row + ((M - MLO) * TAU + FI) * 2) = make_float2(fr, fi2);
    if constexpr (M < MHI) frag_ms<L, TAU, FI, L1, L2, MLO, MHI, M + 1>(row, xr, xi);
}

// Per-WARP cooperative coalesced store of one staged chunk (32 rows).
// CHUNK floats per element (even), OFF = float offset inside the 512-float row.
// Moderate unroll (4) keeps peak register pressure at the proven 128-reg level.
template <int CHUNK, int OFF>
__device__ __forceinline__ void store_stage(const float* smw, float* __restrict__ out,
                                            int wbase, int lane) {
    __syncwarp();
    constexpr int C2 = CHUNK / 2;
    #pragma unroll 4
    for (int u = lane; u < 32 * C2; u += 32) {
        const int e = u / C2;
        const int j = u - e * C2;
        const float2 v = *reinterpret_cast<const float2*>(smw + e * STRIDE + 2 * j);
        *reinterpret_cast<float2*>(out + (size_t)(wbase + e) * 512 + OFF + 2 * j) = v;
    }
    __syncwarp();
}

// ---------------------------------------------------------------------------
// Main kernel: one thread per batch element; warp-private smem staging,
// warp-level syncs only (warps fully decoupled). 4 CTAs/SM = 128-reg budget:
// the ONLY configuration measured so far with zero spills. Output layout per
// element (512 floats):
//   l=0: off   0, tau 4  | l=1: off   8, tau 9 | l=2: off  62, tau 11
//   l=3: off 172, tau 10 | l=4: off 312, tau 6 | l=5: off 420, tau 3
//   l=6: off 486, tau 1
// ---------------------------------------------------------------------------
__global__ void __launch_bounds__(TPB, 4)
cgprod_kernel(const float* __restrict__ x0, const float* __restrict__ x1,
              const float* __restrict__ x2, const float* __restrict__ x3,
              float* __restrict__ out) {
    __shared__ float sm[TPB * STRIDE];
    const int tid   = threadIdx.x;
    const int lane  = tid & 31;
    const int warp  = tid >> 5;
    const int wbase = blockIdx.x * TPB + warp * 32;   // first element of this warp
    const int b     = wbase + lane;

    float xr[16], xi[16];
    {
        const float2 v = reinterpret_cast<const float2*>(x0)[b];
        xr[0] = v.x; xi[0] = v.y;
    }
    {
        const float2* p = reinterpret_cast<const float2*>(x1) + (size_t)b * 3;
        #pragma unroll
        for (int k = 0; k < 3; ++k) { const float2 v = p[k]; xr[1 + k] = v.x; xi[1 + k] = v.y; }
    }
    {
        const float2* p = reinterpret_cast<const float2*>(x2) + (size_t)b * 5;
        #pragma unroll
        for (int k = 0; k < 5; ++k) { const float2 v = p[k]; xr[4 + k] = v.x; xi[4 + k] = v.y; }
    }
    {
        const float2* p = reinterpret_cast<const float2*>(x3) + (size_t)b * 7;
        #pragma unroll
        for (int k = 0; k < 7; ++k) { const float2 v = p[k]; xr[9 + k] = v.x; xi[9 + k] = v.y; }
    }

    float* smw = sm + warp * 32 * STRIDE;   // this warp's 32-row staging region
    float* row = smw + lane * STRIDE;       // this lane's row

    // ---- l = 0 (tau=4), m = 0: chunk 8 @ off 0 ----
    {
        constexpr int L = 0, TAU = 4, MLO = 0, MHI = 0;
        frag_ms<L, TAU, 0, 0, 0, MLO, MHI, MLO>(row, xr, xi);
        frag_ms<L, TAU, 1, 1, 1, MLO, MHI, MLO>(row, xr, xi);
        frag_ms<L, TAU, 2, 2, 2, MLO, MHI, MLO>(row, xr, xi);
        frag_ms<L, TAU, 3, 3, 3, MLO, MHI, MLO>(row, xr, xi);
    }
    store_stage<8, 0>(smw, out, wbase, lane);

    // ---- l = 1 (tau=9) ----
    #define L1_FRAGS(MLO, MHI)                                   \
        { constexpr int L = 1, TAU = 9;                          \
          frag_ms<L, TAU, 0, 0, 1, MLO, MHI, MLO>(row, xr, xi);  \
          frag_ms<L, TAU, 1, 1, 0, MLO, MHI, MLO>(row, xr, xi);  \
          frag_ms<L, TAU, 2, 1, 1, MLO, MHI, MLO>(row, xr, xi);  \
          frag_ms<L, TAU, 3, 1, 2, MLO, MHI, MLO>(row, xr, xi);  \
          frag_ms<L, TAU, 4, 2, 1, MLO, MHI, MLO>(row, xr, xi);  \
          frag_ms<L, TAU, 5, 2, 2, MLO, MHI, MLO>(row, xr, xi);  \
          frag_ms<L, TAU, 6, 2, 3, MLO, MHI, MLO>(row, xr, xi);  \
          frag_ms<L, TAU, 7, 3, 2, MLO, MHI, MLO>(row, xr, xi);  \
          frag_ms<L, TAU, 8, 3, 3, MLO, MHI, MLO>(row, xr, xi); }
    L1_FRAGS(-1, 0)  store_stage<36, 8>(smw, out, wbase, lane);    // m=-1..0
    L1_FRAGS( 1, 1)  store_stage<18, 44>(smw, out, wbase, lane);   // m=1

    // ---- l = 2 (tau=11) ----
    #define L2_FRAGS(MLO, MHI)                                    \
        { constexpr int L = 2, TAU = 11;                          \
          frag_ms<L, TAU,  0, 0, 2, MLO, MHI, MLO>(row, xr, xi);  \
          frag_ms<L, TAU,  1, 1, 1, MLO, MHI, MLO>(row, xr, xi);  \
          frag_ms<L, TAU,  2, 1, 2, MLO, MHI, MLO>(row, xr, xi);  \
          frag_ms<L, TAU,  3, 1, 3, MLO, MHI, MLO>(row, xr, xi);  \
          frag_ms<L, TAU,  4, 2, 0, MLO, MHI, MLO>(row, xr, xi);  \
          frag_ms<L, TAU,  5, 2, 1, MLO, MHI, MLO>(row, xr, xi);  \
          frag_ms<L, TAU,  6, 2, 2, MLO, MHI, MLO>(row, xr, xi);  \
          frag_ms<L, TAU,  7, 2, 3, MLO, MHI, MLO>(row, xr, xi);  \
          frag_ms<L, TAU,  8, 3, 1, MLO, MHI, MLO>(row, xr, xi);  \
          frag_ms<L, TAU,  9, 3, 2, MLO, MHI, MLO>(row, xr, xi);  \
          frag_ms<L, TAU, 10, 3, 3, MLO, MHI, MLO>(row, xr, xi); }
    L2_FRAGS(-2, -1) store_stage<44, 62>(smw, out, wbase, lane);   // m=-2..-1
    L2_FRAGS( 0,  1) store_stage<44, 106>(smw, out, wbase, lane);  // m=0..1
    L2_FRAGS( 2,  2) store_stage<22, 150>(smw, out, wbase, lane);  // m=2

    // ---- l = 3 (tau=10) ----
    #define L3_FRAGS(MLO, MHI)                                   \
        { constexpr int L = 3, TAU = 10;                         \
          frag_ms<L, TAU, 0, 0, 3, MLO, MHI, MLO>(row, xr, xi);  \
          frag_ms<L, TAU, 1, 1, 2, MLO, MHI, MLO>(row, xr, xi);  \
          frag_ms<L, TAU, 2, 1, 3, MLO, MHI, MLO>(row, xr, xi);  \
          frag_ms<L, TAU, 3, 2, 1, MLO, MHI, MLO>(row, xr, xi);  \
          frag_ms<L, TAU, 4, 2, 2, MLO, MHI, MLO>(row, xr, xi);  \
          frag_ms<L, TAU, 5, 2, 3, MLO, MHI, MLO>(row, xr, xi);  \
          frag_ms<L, TAU, 6, 3, 0, MLO, MHI, MLO>(row, xr, xi);  \
          frag_ms<L, TAU, 7, 3, 1, MLO, MHI, MLO>(row, xr, xi);  \
          frag_ms<L, TAU, 8, 3, 2, MLO, MHI, MLO>(row, xr, xi);  \
          frag_ms<L, TAU, 9, 3, 3, MLO, MHI, MLO>(row, xr, xi); }
    L3_FRAGS(-3, -2) store_stage<40, 172>(smw, out, wbase, lane);  // m=-3..-2
    L3_FRAGS(-1,  0) store_stage<40, 212>(smw, out, wbase, lane);  // m=-1..0
    L3_FRAGS( 1,  2) store_stage<40, 252>(smw, out, wbase, lane);  // m=1..2
    L3_FRAGS( 3,  3) store_stage<20, 292>(smw, out, wbase, lane);  // m=3

    // ---- l = 4 (tau=6) ----
    #define L4_FRAGS(MLO, MHI)                                   \
        { constexpr int L = 4, TAU = 6;                          \
          frag_ms<L, TAU, 0, 1, 3, MLO, MHI, MLO>(row, xr, xi);  \
          frag_ms<L, TAU, 1, 2, 2, MLO, MHI, MLO>(row, xr, xi);  \
          frag_ms<L, TAU, 2, 2, 3, MLO, MHI, MLO>(row, xr, xi);  \
          frag_ms<L, TAU, 3, 3, 1, MLO, MHI, MLO>(row, xr, xi);  \
          frag_ms<L, TAU, 4, 3, 2, MLO, MHI, MLO>(row, xr, xi);  \
          frag_ms<L, TAU, 5, 3, 3, MLO, MHI, MLO>(row, xr, xi); }
    L4_FRAGS(-4, -2) store_stage<36, 312>(smw, out, wbase, lane);  // m=-4..-2
    L4_FRAGS(-1,  1) store_stage<36, 348>(smw, out, wbase, lane);  // m=-1..1
    L4_FRAGS( 2,  4) store_stage<36, 384>(smw, out, wbase, lane);  // m=2..4

    // ---- l = 5 (tau=3) ----
    #define L5_FRAGS(MLO, MHI)                                   \
        { constexpr int L = 5, TAU = 3;                          \
          frag_ms<L, TAU, 0, 2, 3, MLO, MHI, MLO>(row, xr, xi);  \
          frag_ms<L, TAU, 1, 3, 2, MLO, MHI, MLO>(row, xr, xi);  \
          frag_ms<L, TAU, 2, 3, 3, MLO, MHI, MLO>(row, xr, xi); }
    L5_FRAGS(-5, 1)  store_stage<42, 420>(smw, out, wbase, lane);  // m=-5..1
    L5_FRAGS( 2, 5)  store_stage<24, 462>(smw, out, wbase, lane);  // m=2..5

    // ---- l = 6 (tau=1), m = -6..6: chunk 26 @ off 486 ----
    {
        constexpr int L = 6, TAU = 1, MLO = -6, MHI = 6;
        frag_ms<L, TAU, 0, 3, 3, MLO, MHI, MLO>(row, xr, xi);
    }
    store_stage<26, 486>(smw, out, wbase, lane);
}

extern "C" void kernel_launch(void* const* d_in, const int* in_sizes, int n_in,
                              void* d_out, int out_size) {
    // Defensive: map inputs by element count (all four are distinct).
    const float* xp[4] = {nullptr, nullptr, nullptr, nullptr};
    for (int i = 0; i < n_in && i < 8; ++i) {
        const int s = in_sizes[i];
        if      (s == NB * 2)  xp[0] = (const float*)d_in[i];
        else if (s == NB * 6)  xp[1] = (const float*)d_in[i];
        else if (s == NB * 10) xp[2] = (const float*)d_in[i];
        else if (s == NB * 14) xp[3] = (const float*)d_in[i];
    }
    cgprod_kernel<<<NB / TPB, TPB>>>(xp[0], xp[1], xp[2], xp[3], (float*)d_out);
}

// round 10
// speedup vs baseline: 2.7580x; 1.3802x over previous
#include <cuda_runtime.h>
#include <cstddef>

#define TPB 128              // 4 warps/block, each warp owns 32 elements
#define STRIDE 94            // floats per smem row: >= max chunk (90), gcd(94,32)=2

static constexpr int NB = 131072;

// ---------------------------------------------------------------------------
// Compile-time Clebsch-Gordan coefficients (Racah formula), double precision,
// evaluated entirely by the compiler (constexpr Newton sqrt).
// ---------------------------------------------------------------------------
__host__ __device__ constexpr double factd(int n) {
    double r = 1.0;
    for (int i = 2; i <= n; ++i) r *= (double)i;
    return r;
}
__host__ __device__ constexpr double csqrt(double x) {
    if (x <= 0.0) return 0.0;
    double g = x > 1.0 ? x : 1.0;
    for (int i = 0; i < 100; ++i) g = 0.5 * (g + x / g);
    return g;
}
__host__ __device__ constexpr int iabs_c(int x) { return x < 0 ? -x : x; }
__host__ __device__ constexpr int imin6(int a, int b, int c, int d, int e, int f) {
    int m = a;
    if (b < m) m = b; if (c < m) m = c; if (d < m) m = d;
    if (e < m) m = e; if (f < m) m = f;
    return m;
}

__host__ __device__ constexpr double cgco(int j1, int m1, int j2, int m2, int j, int m) {
    if (m1 + m2 != m) return 0.0;
    if (j < iabs_c(j1 - j2) || j > j1 + j2) return 0.0;
    if (iabs_c(m) > j || iabs_c(m1) > j1 || iabs_c(m2) > j2) return 0.0;
    double pre = csqrt((2.0 * j + 1.0) * factd(j1 + j2 - j) * factd(j + j1 - j2) *
                       factd(j + j2 - j1) / factd(j1 + j2 + j + 1));
    pre *= csqrt(factd(j + m) * factd(j - m) * factd(j1 + m1) * factd(j1 - m1) *
                 factd(j2 + m2) * factd(j2 - m2));
    double s = 0.0;
    for (int k = 0; k <= j1 + j2 - j; ++k) {
        const int d1 = k;
        const int d2 = j1 + j2 - j - k;
        const int d3 = j1 - m1 - k;
        const int d4 = j2 + m2 - k;
        const int d5 = j - j2 + m1 + k;
        const int d6 = j - j1 - m2 + k;
        if (imin6(d1, d2, d3, d4, d5, d6) < 0) continue;
        const double denom = factd(d1) * factd(d2) * factd(d3) * factd(d4) * factd(d5) * factd(d6);
        s += ((k & 1) ? -1.0 : 1.0) / denom;
    }
    return pre * s;
}

// Register-array offset for input part l (sizes 1,3,5,7 -> offsets 0,1,4,9)
template <int L>
__host__ __device__ constexpr int xoff() { return L == 0 ? 0 : (L == 1 ? 1 : (L == 2 ? 4 : 9)); }

// ---------------------------------------------------------------------------
// Template-unrolled accumulation: sum over m1 for one (l1,l2,l,m) entry set.
// All CG coefficients become FFMA immediates; zero coefficients pruned.
// ---------------------------------------------------------------------------
template <int L1, int L2, int L, int M, int M1>
__device__ __forceinline__ void acc_m1(float& fr, float& fi, const float* xr, const float* xi) {
    constexpr int M2 = M - M1;
    if constexpr (M2 >= -L2 && M2 <= L2) {
        constexpr double Cd = cgco(L1, M1, L2, M2, L, M);
        if constexpr (Cd != 0.0) {
            constexpr float C = (float)Cd;
            const float a = xr[xoff<L1>() + M1 + L1];
            const float b = xi[xoff<L1>() + M1 + L1];
            const float c = xr[xoff<L2>() + M2 + L2];
            const float d = xi[xoff<L2>() + M2 + L2];
            const float pr = fmaf(-b, d, a * c);   // Re(x*y)
            const float pi = fmaf( b, c, a * d);   // Im(x*y)
            fr = fmaf(C, pr, fr);
            fi = fmaf(C, pi, fi);
        }
    }
    if constexpr (M1 < L1) acc_m1<L1, L2, L, M, M1 + 1>(fr, fi, xr, xi);
}

// One fragment (l1,l2) contributing to output l, for m in [MLO, MHI].
// Writes (fr,fi) as ONE float2 (STS.64) into the lane's smem row at stage
// position BASE + ((m-MLO)*TAU + FI)*2 (always even -> 8B aligned).
template <int BASE, int L, int TAU, int FI, int L1, int L2, int MLO, int MHI, int M>
__device__ __forceinline__ void frag_ms(float* row, const float* xr, const float* xi) {
    float fr = 0.0f, fi2 = 0.0f;
    acc_m1<L1, L2, L, M, (-L1)>(fr, fi2, xr, xi);
    *reinterpret_cast<float2*>(row + BASE + ((M - MLO) * TAU + FI) * 2) = make_float2(fr, fi2);
    if constexpr (M < MHI) frag_ms<BASE, L, TAU, FI, L1, L2, MLO, MHI, M + 1>(row, xr, xi);
}

// Per-WARP cooperative coalesced store of one staged chunk (32 rows).
// CHUNK floats per element (even), OFF = float offset inside the 512-float row.
template <int CHUNK, int OFF>
__device__ __forceinline__ void store_stage(const float* smw, float* __restrict__ out,
                                            int wbase, int lane) {
    __syncwarp();
    constexpr int C2 = CHUNK / 2;
    #pragma unroll 4
    for (int u = lane; u < 32 * C2; u += 32) {
        const int e = u / C2;
        const int j = u - e * C2;
        const float2 v = *reinterpret_cast<const float2*>(smw + e * STRIDE + 2 * j);
        *reinterpret_cast<float2*>(out + (size_t)(wbase + e) * 512 + OFF + 2 * j) = v;
    }
    __syncwarp();
}

// ---------------------------------------------------------------------------
// Main kernel: one thread per batch element; warp-private smem staging with
// warp-level syncs only. 7 mega-stages (chunks 62/88/82/80/72/90/38) pack
// multiple l-chunks contiguously, minimizing sync count and keeping every
// store run long and coalesced. 4 CTAs/SM = 128-reg budget (only proven
// spill-free configuration). Output layout per element (512 floats):
//   l=0 @0(8)  l=1 @8(54)  l=2 @62(110)  l=3 @172(140)
//   l=4 @312(108)  l=5 @420(66)  l=6 @486(26)
// ---------------------------------------------------------------------------
__global__ void __launch_bounds__(TPB, 4)
cgprod_kernel(const float* __restrict__ x0, const float* __restrict__ x1,
              const float* __restrict__ x2, const float* __restrict__ x3,
              float* __restrict__ out) {
    __shared__ float sm[TPB * STRIDE];   // 48128 B (< 48KB static limit)
    const int tid   = threadIdx.x;
    const int lane  = tid & 31;
    const int warp  = tid >> 5;
    const int wbase = blockIdx.x * TPB + warp * 32;   // first element of this warp
    const int b     = wbase + lane;

    float xr[16], xi[16];
    {
        const float2 v = reinterpret_cast<const float2*>(x0)[b];
        xr[0] = v.x; xi[0] = v.y;
    }
    {
        const float2* p = reinterpret_cast<const float2*>(x1) + (size_t)b * 3;
        #pragma unroll
        for (int k = 0; k < 3; ++k) { const float2 v = p[k]; xr[1 + k] = v.x; xi[1 + k] = v.y; }
    }
    {
        const float2* p = reinterpret_cast<const float2*>(x2) + (size_t)b * 5;
        #pragma unroll
        for (int k = 0; k < 5; ++k) { const float2 v = p[k]; xr[4 + k] = v.x; xi[4 + k] = v.y; }
    }
    {
        const float2* p = reinterpret_cast<const float2*>(x3) + (size_t)b * 7;
        #pragma unroll
        for (int k = 0; k < 7; ++k) { const float2 v = p[k]; xr[9 + k] = v.x; xi[9 + k] = v.y; }
    }

    float* smw = sm + warp * 32 * STRIDE;   // this warp's 32-row staging region
    float* row = smw + lane * STRIDE;       // this lane's row

    // ================= Stage 1: l0 (all) + l1 (all m) : 62 floats @ 0 =====
    {   // l0: tau=4, m=0, BASE 0
        frag_ms<0, 0, 4, 0, 0, 0, 0, 0, 0>(row, xr, xi);
        frag_ms<0, 0, 4, 1, 1, 1, 0, 0, 0>(row, xr, xi);
        frag_ms<0, 0, 4, 2, 2, 2, 0, 0, 0>(row, xr, xi);
        frag_ms<0, 0, 4, 3, 3, 3, 0, 0, 0>(row, xr, xi);
        // l1: tau=9, m=-1..1, BASE 8
        frag_ms<8, 1, 9, 0, 0, 1, -1, 1, -1>(row, xr, xi);
        frag_ms<8, 1, 9, 1, 1, 0, -1, 1, -1>(row, xr, xi);
        frag_ms<8, 1, 9, 2, 1, 1, -1, 1, -1>(row, xr, xi);
        frag_ms<8, 1, 9, 3, 1, 2, -1, 1, -1>(row, xr, xi);
        frag_ms<8, 1, 9, 4, 2, 1, -1, 1, -1>(row, xr, xi);
        frag_ms<8, 1, 9, 5, 2, 2, -1, 1, -1>(row, xr, xi);
        frag_ms<8, 1, 9, 6, 2, 3, -1, 1, -1>(row, xr, xi);
        frag_ms<8, 1, 9, 7, 3, 2, -1, 1, -1>(row, xr, xi);
        frag_ms<8, 1, 9, 8, 3, 3, -1, 1, -1>(row, xr, xi);
    }
    store_stage<62, 0>(smw, out, wbase, lane);

    // l2 fragment list helper (tau=11)
    #define L2F(BASE, MLO, MHI)                                      \
        frag_ms<BASE, 2, 11,  0, 0, 2, MLO, MHI, MLO>(row, xr, xi);  \
        frag_ms<BASE, 2, 11,  1, 1, 1, MLO, MHI, MLO>(row, xr, xi);  \
        frag_ms<BASE, 2, 11,  2, 1, 2, MLO, MHI, MLO>(row, xr, xi);  \
        frag_ms<BASE, 2, 11,  3, 1, 3, MLO, MHI, MLO>(row, xr, xi);  \
        frag_ms<BASE, 2, 11,  4, 2, 0, MLO, MHI, MLO>(row, xr, xi);  \
        frag_ms<BASE, 2, 11,  5, 2, 1, MLO, MHI, MLO>(row, xr, xi);  \
        frag_ms<BASE, 2, 11,  6, 2, 2, MLO, MHI, MLO>(row, xr, xi);  \
        frag_ms<BASE, 2, 11,  7, 2, 3, MLO, MHI, MLO>(row, xr, xi);  \
        frag_ms<BASE, 2, 11,  8, 3, 1, MLO, MHI, MLO>(row, xr, xi);  \
        frag_ms<BASE, 2, 11,  9, 3, 2, MLO, MHI, MLO>(row, xr, xi);  \
        frag_ms<BASE, 2, 11, 10, 3, 3, MLO, MHI, MLO>(row, xr, xi);

    // l3 fragment list helper (tau=10)
    #define L3F(BASE, MLO, MHI)                                     \
        frag_ms<BASE, 3, 10, 0, 0, 3, MLO, MHI, MLO>(row, xr, xi);  \
        frag_ms<BASE, 3, 10, 1, 1, 2, MLO, MHI, MLO>(row, xr, xi);  \
        frag_ms<BASE, 3, 10, 2, 1, 3, MLO, MHI, MLO>(row, xr, xi);  \
        frag_ms<BASE, 3, 10, 3, 2, 1, MLO, MHI, MLO>(row, xr, xi);  \
        frag_ms<BASE, 3, 10, 4, 2, 2, MLO, MHI, MLO>(row, xr, xi);  \
        frag_ms<BASE, 3, 10, 5, 2, 3, MLO, MHI, MLO>(row, xr, xi);  \
        frag_ms<BASE, 3, 10, 6, 3, 0, MLO, MHI, MLO>(row, xr, xi);  \
        frag_ms<BASE, 3, 10, 7, 3, 1, MLO, MHI, MLO>(row, xr, xi);  \
        frag_ms<BASE, 3, 10, 8, 3, 2, MLO, MHI, MLO>(row, xr, xi);  \
        frag_ms<BASE, 3, 10, 9, 3, 3, MLO, MHI, MLO>(row, xr, xi);

    // l4 fragment list helper (tau=6)
    #define L4F(BASE, MLO, MHI)                                    \
        frag_ms<BASE, 4, 6, 0, 1, 3, MLO, MHI, MLO>(row, xr, xi);  \
        frag_ms<BASE, 4, 6, 1, 2, 2, MLO, MHI, MLO>(row, xr, xi);  \
        frag_ms<BASE, 4, 6, 2, 2, 3, MLO, MHI, MLO>(row, xr, xi);  \
        frag_ms<BASE, 4, 6, 3, 3, 1, MLO, MHI, MLO>(row, xr, xi);  \
        frag_ms<BASE, 4, 6, 4, 3, 2, MLO, MHI, MLO>(row, xr, xi);  \
        frag_ms<BASE, 4, 6, 5, 3, 3, MLO, MHI, MLO>(row, xr, xi);

    // l5 fragment list helper (tau=3)
    #define L5F(BASE, MLO, MHI)                                    \
        frag_ms<BASE, 5, 3, 0, 2, 3, MLO, MHI, MLO>(row, xr, xi);  \
        frag_ms<BASE, 5, 3, 1, 3, 2, MLO, MHI, MLO>(row, xr, xi);  \
        frag_ms<BASE, 5, 3, 2, 3, 3, MLO, MHI, MLO>(row, xr, xi);

    // ================= Stage 2: l2 m=-2..1 : 88 floats @ 62 ==============
    { L2F(0, -2, 1) }
    store_stage<88, 62>(smw, out, wbase, lane);

    // ================= Stage 3: l2 m=2 (22) + l3 m=-3..-1 (60) @ 150 =====
    { L2F(0, 2, 2)  L3F(22, -3, -1) }
    store_stage<82, 150>(smw, out, wbase, lane);

    // ================= Stage 4: l3 m=0..3 : 80 floats @ 232 ==============
    { L3F(0, 0, 3) }
    store_stage<80, 232>(smw, out, wbase, lane);

    // ================= Stage 5: l4 m=-4..1 : 72 floats @ 312 =============
    { L4F(0, -4, 1) }
    store_stage<72, 312>(smw, out, wbase, lane);

    // ================= Stage 6: l4 m=2..4 (36) + l5 m=-5..3 (54) @ 384 ===
    { L4F(0, 2, 4)  L5F(36, -5, 3) }
    store_stage<90, 384>(smw, out, wbase, lane);

    // ================= Stage 7: l5 m=4..5 (12) + l6 all (26) @ 474 =======
    {
        L5F(0, 4, 5)
        frag_ms<12, 6, 1, 0, 3, 3, -6, 6, -6>(row, xr, xi);   // l6 tau=1
    }
    store_stage<38, 474>(smw, out, wbase, lane);
}

extern "C" void kernel_launch(void* const* d_in, const int* in_sizes, int n_in,
                              void* d_out, int out_size) {
    // Defensive: map inputs by element count (all four are distinct).
    const float* xp[4] = {nullptr, nullptr, nullptr, nullptr};
    for (int i = 0; i < n_in && i < 8; ++i) {
        const int s = in_sizes[i];
        if      (s == NB * 2)  xp[0] = (const float*)d_in[i];
        else if (s == NB * 6)  xp[1] = (const float*)d_in[i];
        else if (s == NB * 10) xp[2] = (const float*)d_in[i];
        else if (s == NB * 14) xp[3] = (const float*)d_in[i];
    }
    cgprod_kernel<<<NB / TPB, TPB>>>(xp[0], xp[1], xp[2], xp[3], (float*)d_out);
}

// round 11
// speedup vs baseline: 2.9730x; 1.0780x over previous
#include <cuda_runtime.h>
#include <cstddef>

#define TPB 128              // 4 warps/block, each warp owns 32 elements
#define STRIDE 66            // floats per smem row (stage = 64 floats + pad)

static constexpr int NB = 131072;

// ---------------------------------------------------------------------------
// Compile-time Clebsch-Gordan coefficients (Racah formula), double precision,
// evaluated entirely by the compiler (constexpr Newton sqrt).
// ---------------------------------------------------------------------------
__host__ __device__ constexpr double factd(int n) {
    double r = 1.0;
    for (int i = 2; i <= n; ++i) r *= (double)i;
    return r;
}
__host__ __device__ constexpr double csqrt(double x) {
    if (x <= 0.0) return 0.0;
    double g = x > 1.0 ? x : 1.0;
    for (int i = 0; i < 100; ++i) g = 0.5 * (g + x / g);
    return g;
}
__host__ __device__ constexpr int iabs_c(int x) { return x < 0 ? -x : x; }
__host__ __device__ constexpr int imin6(int a, int b, int c, int d, int e, int f) {
    int m = a;
    if (b < m) m = b; if (c < m) m = c; if (d < m) m = d;
    if (e < m) m = e; if (f < m) m = f;
    return m;
}

__host__ __device__ constexpr double cgco(int j1, int m1, int j2, int m2, int j, int m) {
    if (m1 + m2 != m) return 0.0;
    if (j < iabs_c(j1 - j2) || j > j1 + j2) return 0.0;
    if (iabs_c(m) > j || iabs_c(m1) > j1 || iabs_c(m2) > j2) return 0.0;
    double pre = csqrt((2.0 * j + 1.0) * factd(j1 + j2 - j) * factd(j + j1 - j2) *
                       factd(j + j2 - j1) / factd(j1 + j2 + j + 1));
    pre *= csqrt(factd(j + m) * factd(j - m) * factd(j1 + m1) * factd(j1 - m1) *
                 factd(j2 + m2) * factd(j2 - m2));
    double s = 0.0;
    for (int k = 0; k <= j1 + j2 - j; ++k) {
        const int d1 = k;
        const int d2 = j1 + j2 - j - k;
        const int d3 = j1 - m1 - k;
        const int d4 = j2 + m2 - k;
        const int d5 = j - j2 + m1 + k;
        const int d6 = j - j1 - m2 + k;
        if (imin6(d1, d2, d3, d4, d5, d6) < 0) continue;
        const double denom = factd(d1) * factd(d2) * factd(d3) * factd(d4) * factd(d5) * factd(d6);
        s += ((k & 1) ? -1.0 : 1.0) / denom;
    }
    return pre * s;
}

// Register-array offset for input part l (sizes 1,3,5,7 -> offsets 0,1,4,9)
template <int L>
__host__ __device__ constexpr int xoff() { return L == 0 ? 0 : (L == 1 ? 1 : (L == 2 ? 4 : 9)); }

// ---------------------------------------------------------------------------
// Template-unrolled accumulation: sum over m1 for one (l1,l2,l,m) entry set.
// All CG coefficients become FFMA immediates; zero coefficients pruned.
// ---------------------------------------------------------------------------
template <int L1, int L2, int L, int M, int M1>
__device__ __forceinline__ void acc_m1(float& fr, float& fi, const float* xr, const float* xi) {
    constexpr int M2 = M - M1;
    if constexpr (M2 >= -L2 && M2 <= L2) {
        constexpr double Cd = cgco(L1, M1, L2, M2, L, M);
        if constexpr (Cd != 0.0) {
            constexpr float C = (float)Cd;
            const float a = xr[xoff<L1>() + M1 + L1];
            const float b = xi[xoff<L1>() + M1 + L1];
            const float c = xr[xoff<L2>() + M2 + L2];
            const float d = xi[xoff<L2>() + M2 + L2];
            const float pr = fmaf(-b, d, a * c);   // Re(x*y)
            const float pi = fmaf( b, c, a * d);   // Im(x*y)
            fr = fmaf(C, pr, fr);
            fi = fmaf(C, pi, fi);
        }
    }
    if constexpr (M1 < L1) acc_m1<L1, L2, L, M, M1 + 1>(fr, fi, xr, xi);
}

// One fragment (l1,l2,l,m): accumulate and write the (fr,fi) pair as ONE
// float2 (STS.64) at stage-relative float position POS (always even).
template <int POS, int L, int L1, int L2, int M>
__device__ __forceinline__ void frag1(float* row, const float* xr, const float* xi) {
    float fr = 0.0f, fi = 0.0f;
    acc_m1<L1, L2, L, M, (-L1)>(fr, fi, xr, xi);
    *reinterpret_cast<float2*>(row + POS) = make_float2(fr, fi);
}

// Per-WARP store of one 64-float stage for 32 elements. Division-free,
// fully affine addressing: lane j holds float2 #j of each element; loop
// over elements e with src += STRIDE, dst += 512. Each iteration writes
// 256 contiguous bytes (2 full cache lines) per element.
template <int STAGE>
__device__ __forceinline__ void store64(const float* smw, float* __restrict__ out,
                                        int wbase, int lane) {
    __syncwarp();
    const float* src = smw + 2 * lane;
    float* dst = out + (size_t)wbase * 512 + STAGE * 64 + 2 * lane;
    #pragma unroll 4
    for (int e = 0; e < 32; ++e) {
        const float2 v = *reinterpret_cast<const float2*>(src + e * STRIDE);
        *reinterpret_cast<float2*>(dst + (size_t)e * 512) = v;
    }
    __syncwarp();
}

#define F1(POS, L, L1, L2, M) frag1<POS, L, L1, L2, M>(row, xr, xi);

// Full m-run emitters: all fragments of output part L at one m, pair FI at
// stage-relative position POS + 2*FI. Fragment order = gelib (l1 outer).
#define L0RUN(POS)                                                          \
    F1(POS + 0, 0, 0, 0, 0) F1(POS + 2, 0, 1, 1, 0)                         \
    F1(POS + 4, 0, 2, 2, 0) F1(POS + 6, 0, 3, 3, 0)
#define L1RUN(POS, M)                                                       \
    F1(POS + 0,  1, 0, 1, M) F1(POS + 2,  1, 1, 0, M) F1(POS + 4,  1, 1, 1, M) \
    F1(POS + 6,  1, 1, 2, M) F1(POS + 8,  1, 2, 1, M) F1(POS + 10, 1, 2, 2, M) \
    F1(POS + 12, 1, 2, 3, M) F1(POS + 14, 1, 3, 2, M) F1(POS + 16, 1, 3, 3, M)
#define L2RUN(POS, M)                                                       \
    F1(POS + 0,  2, 0, 2, M) F1(POS + 2,  2, 1, 1, M) F1(POS + 4,  2, 1, 2, M) \
    F1(POS + 6,  2, 1, 3, M) F1(POS + 8,  2, 2, 0, M) F1(POS + 10, 2, 2, 1, M) \
    F1(POS + 12, 2, 2, 2, M) F1(POS + 14, 2, 2, 3, M) F1(POS + 16, 2, 3, 1, M) \
    F1(POS + 18, 2, 3, 2, M) F1(POS + 20, 2, 3, 3, M)
#define L3RUN(POS, M)                                                       \
    F1(POS + 0,  3, 0, 3, M) F1(POS + 2,  3, 1, 2, M) F1(POS + 4,  3, 1, 3, M) \
    F1(POS + 6,  3, 2, 1, M) F1(POS + 8,  3, 2, 2, M) F1(POS + 10, 3, 2, 3, M) \
    F1(POS + 12, 3, 3, 0, M) F1(POS + 14, 3, 3, 1, M) F1(POS + 16, 3, 3, 2, M) \
    F1(POS + 18, 3, 3, 3, M)
#define L4RUN(POS, M)                                                       \
    F1(POS + 0,  4, 1, 3, M) F1(POS + 2,  4, 2, 2, M) F1(POS + 4,  4, 2, 3, M) \
    F1(POS + 6,  4, 3, 1, M) F1(POS + 8,  4, 3, 2, M) F1(POS + 10, 4, 3, 3, M)
#define L5RUN(POS, M)                                                       \
    F1(POS + 0, 5, 2, 3, M) F1(POS + 2, 5, 3, 2, M) F1(POS + 4, 5, 3, 3, M)

// ---------------------------------------------------------------------------
// Main kernel: one thread per batch element; warp-private smem staging with
// warp-level syncs only; 8 stages of exactly 64 output floats each (512=8*64).
// Output layout per element (512 floats):
//   l=0 @0(8)  l=1 @8(54)  l=2 @62(110)  l=3 @172(140)
//   l=4 @312(108)  l=5 @420(66)  l=6 @486(26)
// m-runs split at fragment granularity across stage boundaries (pairs are
// even-aligned, boundaries even -> no pair straddles; no recomputation).
// 4 CTAs/SM = 128-reg budget (only proven spill-free configuration).
// ---------------------------------------------------------------------------
__global__ void __launch_bounds__(TPB, 4)
cgprod_kernel(const float* __restrict__ x0, const float* __restrict__ x1,
              const float* __restrict__ x2, const float* __restrict__ x3,
              float* __restrict__ out) {
    __shared__ float sm[TPB * STRIDE];   // 33792 B
    const int tid   = threadIdx.x;
    const int lane  = tid & 31;
    const int warp  = tid >> 5;
    const int wbase = blockIdx.x * TPB + warp * 32;   // first element of this warp
    const int b     = wbase + lane;

    float xr[16], xi[16];
    {
        const float2 v = reinterpret_cast<const float2*>(x0)[b];
        xr[0] = v.x; xi[0] = v.y;
    }
    {
        const float2* p = reinterpret_cast<const float2*>(x1) + (size_t)b * 3;
        #pragma unroll
        for (int k = 0; k < 3; ++k) { const float2 v = p[k]; xr[1 + k] = v.x; xi[1 + k] = v.y; }
    }
    {
        const float2* p = reinterpret_cast<const float2*>(x2) + (size_t)b * 5;
        #pragma unroll
        for (int k = 0; k < 5; ++k) { const float2 v = p[k]; xr[4 + k] = v.x; xi[4 + k] = v.y; }
    }
    {
        const float2* p = reinterpret_cast<const float2*>(x3) + (size_t)b * 7;
        #pragma unroll
        for (int k = 0; k < 7; ++k) { const float2 v = p[k]; xr[9 + k] = v.x; xi[9 + k] = v.y; }
    }

    float* smw = sm + warp * 32 * STRIDE;   // this warp's 32-row staging region
    float* row = smw + lane * STRIDE;       // this lane's row

    // ===== Stage 0: out [0,64) = l0 all | l1 m=-1,0,1 | l2 m=-2 FI0 ======
    {
        L0RUN(0)
        L1RUN(8, -1) L1RUN(26, 0) L1RUN(44, 1)
        F1(62, 2, 0, 2, -2)                       // l2 m=-2, FI=0 (0,2)
    }
    store64<0>(smw, out, wbase, lane);

    // ===== Stage 1: out [64,128) = l2 m=-2 FI1..10 | m=-1 | m=0 ==========
    {
        F1(0, 2, 1, 1, -2) F1(2, 2, 1, 2, -2) F1(4, 2, 1, 3, -2)
        F1(6, 2, 2, 0, -2) F1(8, 2, 2, 1, -2) F1(10, 2, 2, 2, -2)
        F1(12, 2, 2, 3, -2) F1(14, 2, 3, 1, -2) F1(16, 2, 3, 2, -2)
        F1(18, 2, 3, 3, -2)
        L2RUN(20, -1) L2RUN(42, 0)
    }
    store64<1>(smw, out, wbase, lane);

    // ===== Stage 2: out [128,192) = l2 m=1 | l2 m=2 | l3 m=-3 ============
    {
        L2RUN(0, 1) L2RUN(22, 2) L3RUN(44, -3)
    }
    store64<2>(smw, out, wbase, lane);

    // ===== Stage 3: out [192,256) = l3 m=-2,-1,0 | l3 m=1 FI0..1 =========
    {
        L3RUN(0, -2) L3RUN(20, -1) L3RUN(40, 0)
        F1(60, 3, 0, 3, 1) F1(62, 3, 1, 2, 1)     // l3 m=1, FI 0..1
    }
    store64<3>(smw, out, wbase, lane);

    // ===== Stage 4: out [256,320) = l3 m=1 FI2..9 | m=2 | m=3 | l4 m=-4 FI0..3
    {
        F1(0, 3, 1, 3, 1) F1(2, 3, 2, 1, 1) F1(4, 3, 2, 2, 1)
        F1(6, 3, 2, 3, 1) F1(8, 3, 3, 0, 1) F1(10, 3, 3, 1, 1)
        F1(12, 3, 3, 2, 1) F1(14, 3, 3, 3, 1)
        L3RUN(16, 2) L3RUN(36, 3)
        F1(56, 4, 1, 3, -4) F1(58, 4, 2, 2, -4)   // l4 m=-4, FI 0..3
        F1(60, 4, 2, 3, -4) F1(62, 4, 3, 1, -4)
    }
    store64<4>(smw, out, wbase, lane);

    // ===== Stage 5: out [320,384) = l4 m=-4 FI4..5 | m=-3..1 =============
    {
        F1(0, 4, 3, 2, -4) F1(2, 4, 3, 3, -4)     // l4 m=-4, FI 4..5
        L4RUN(4, -3) L4RUN(16, -2) L4RUN(28, -1) L4RUN(40, 0) L4RUN(52, 1)
    }
    store64<5>(smw, out, wbase, lane);

    // ===== Stage 6: out [384,448) = l4 m=2,3,4 | l5 m=-5..-2 | l5 m=-1 FI0..1
    {
        L4RUN(0, 2) L4RUN(12, 3) L4RUN(24, 4)
        L5RUN(36, -5) L5RUN(42, -4) L5RUN(48, -3) L5RUN(54, -2)
        F1(60, 5, 2, 3, -1) F1(62, 5, 3, 2, -1)   // l5 m=-1, FI 0..1
    }
    store64<6>(smw, out, wbase, lane);

    // ===== Stage 7: out [448,512) = l5 m=-1 FI2 | m=0..5 | l6 all ========
    {
        F1(0, 5, 3, 3, -1)                        // l5 m=-1, FI 2
        L5RUN(2, 0) L5RUN(8, 1) L5RUN(14, 2) L5RUN(20, 3) L5RUN(26, 4) L5RUN(32, 5)
        F1(38, 6, 3, 3, -6) F1(40, 6, 3, 3, -5) F1(42, 6, 3, 3, -4)
        F1(44, 6, 3, 3, -3) F1(46, 6, 3, 3, -2) F1(48, 6, 3, 3, -1)
        F1(50, 6, 3, 3,  0) F1(52, 6, 3, 3,  1) F1(54, 6, 3, 3,  2)
        F1(56, 6, 3, 3,  3) F1(58, 6, 3, 3,  4) F1(60, 6, 3, 3,  5)
        F1(62, 6, 3, 3,  6)
    }
    store64<7>(smw, out, wbase, lane);
}

extern "C" void kernel_launch(void* const* d_in, const int* in_sizes, int n_in,
                              void* d_out, int out_size) {
    // Defensive: map inputs by element count (all four are distinct).
    const float* xp[4] = {nullptr, nullptr, nullptr, nullptr};
    for (int i = 0; i < n_in && i < 8; ++i) {
        const int s = in_sizes[i];
        if      (s == NB * 2)  xp[0] = (const float*)d_in[i];
        else if (s == NB * 6)  xp[1] = (const float*)d_in[i];
        else if (s == NB * 10) xp[2] = (const float*)d_in[i];
        else if (s == NB * 14) xp[3] = (const float*)d_in[i];
    }
    cgprod_kernel<<<NB / TPB, TPB>>>(xp[0], xp[1], xp[2], xp[3], (float*)d_out);
}